// round 5
// baseline (speedup 1.0000x reference)
#include <cuda_runtime.h>
#include <cstdint>

// Problem dims
#define TT    512
#define BB    32
#define DD    512
#define HH    512
#define FEAT  2048
#define G4H   2048   // 4*H

// Output layout (fp32, tuple order: out, h_n, c_n, x, lens_s)
#define OUT_OFF  0
#define HN_OFF   16777216
#define CN_OFF   (16777216 + 32768)
#define X_OFF    (16777216 + 65536)
#define LENS_OFF (X_OFF + 8388608)

#define GSZ       (512*32*2048)        // per-direction G size (floats)
#define NCTA_SCAN 128
#define SCAN_SMEM ((16384 + 32*516) * 4)

#define WCHUNKS   524288               // frag chunks per weight matrix

// ---------------- device scratch ---------------------------------------
__device__ float    g_G[2 * GSZ];          // input-gate preactivations (268MB)
__device__ float    g_hbuf[4 * 16384];     // [dir][pingpong][32][512]
__device__ int      g_order[BB];
__device__ int      g_lens[BB];
__device__ unsigned g_bar;
__device__ uint4    g_wfc[WCHUNKS];        // fc_w   frag-layout (hi/lo tf32)
__device__ uint4    g_wih[2][WCHUNKS];     // w_ih_f / w_ih_b frag-layout

// ---------------- helpers ----------------------------------------------
__device__ __forceinline__ uint32_t f2tf32(float v) {
    uint32_t r;
    asm("cvt.rna.tf32.f32 %0, %1;" : "=r"(r) : "f"(v));
    return r;
}

__device__ __forceinline__ void mma_tf32(float4& c, const uint4& a,
                                         uint32_t b0, uint32_t b1) {
    asm volatile(
        "mma.sync.aligned.m16n8k8.row.col.f32.tf32.tf32.f32 "
        "{%0,%1,%2,%3}, {%4,%5,%6,%7}, {%8,%9}, {%0,%1,%2,%3};"
        : "+f"(c.x), "+f"(c.y), "+f"(c.z), "+f"(c.w)
        : "r"(a.x), "r"(a.y), "r"(a.z), "r"(a.w), "r"(b0), "r"(b1));
}

#define FMA2(acc, a, b) \
    asm("fma.rn.f32x2 %0, %1, %2, %0;" : "+l"(acc) : "l"(a), "l"(b))

__device__ __forceinline__ float sum2(unsigned long long v) {
    float lo, hi;
    asm("mov.b64 {%0,%1}, %2;" : "=f"(lo), "=f"(hi) : "l"(v));
    return lo + hi;
}

// ---------------- reset / sort kernel ----------------------------------
__global__ void k_reset(const int* __restrict__ seq_lens,
                        const float* __restrict__ h0,
                        float* __restrict__ out) {
    int tid = threadIdx.x;
    if (tid == 0) {
        unsigned used = 0u;
        for (int pos = 0; pos < BB; pos++) {
            int best = -1, bl = -1;
            for (int i = 0; i < BB; i++) {
                if (used & (1u << i)) continue;
                int L = seq_lens[i];
                if (L > bl) { bl = L; best = i; }
            }
            used |= 1u << best;
            g_order[pos] = best;
            g_lens[pos]  = bl;
            out[LENS_OFF + pos] = (float)bl;
        }
        g_bar = 0u;
    }
    for (int i = tid; i < 2 * 16384; i += blockDim.x) {
        int dir = i >> 14;
        int r   = i & 16383;
        g_hbuf[(dir * 2 + 0) * 16384 + r] = h0[i];
    }
}

// ---------------- weight pre-conversion to frag layout ------------------
// Chunk index c: lane=c&31, hl=(c>>5)&1, s=(c>>6)&3, q=(c>>8)&3, tile=c>>10,
//   qt = tile & (nKt-1), r64 = tile >> log2(nKt)
// A-frag (m16n8k8, row g=lane>>2, tg=lane&3):
//   chunk = {W[m0+g][kk], W[m0+g+8][kk], W[m0+g][kk+4], W[m0+g+8][kk+4]}
__global__ void __launch_bounds__(256) k_prep(
    const float* __restrict__ fcw, const float* __restrict__ wihf,
    const float* __restrict__ wihb) {
    int z = blockIdx.y;
    const float* src = (z == 0) ? fcw : ((z == 1) ? wihf : wihb);
    uint4* dst = (z == 0) ? g_wfc : g_wih[z - 1];
    int K     = (z == 0) ? FEAT : DD;
    int nKtm1 = (z == 0) ? 63 : 15;
    int nKtsh = (z == 0) ? 6 : 4;

    int c    = blockIdx.x * 256 + threadIdx.x;
    int lane = c & 31;
    int hl   = (c >> 5) & 1;
    int s    = (c >> 6) & 3;
    int q    = (c >> 8) & 3;
    int tile = c >> 10;
    int qt   = tile & nKtm1;
    int r64  = tile >> nKtsh;
    int g    = lane >> 2, tg = lane & 3;
    int m0   = r64 * 64 + s * 16;
    int kk   = qt * 32 + q * 8 + tg;

    float v0 = src[(size_t)(m0 + g)     * K + kk];
    float v1 = src[(size_t)(m0 + g + 8) * K + kk];
    float v2 = src[(size_t)(m0 + g)     * K + kk + 4];
    float v3 = src[(size_t)(m0 + g + 8) * K + kk + 4];
    uint4 o;
    if (hl == 0) {
        o.x = f2tf32(v0); o.y = f2tf32(v1); o.z = f2tf32(v2); o.w = f2tf32(v3);
    } else {
        o.x = f2tf32(v0 - __uint_as_float(f2tf32(v0)));
        o.y = f2tf32(v1 - __uint_as_float(f2tf32(v1)));
        o.z = f2tf32(v2 - __uint_as_float(f2tf32(v2)));
        o.w = f2tf32(v3 - __uint_as_float(f2tf32(v3)));
    }
    dst[c] = o;
}

// ================= MMA GEMMs: A = weights (frag-global), B = data rows ==
// CTA tile: 64 channels (M) x 64 data rows (N) x 32 k. 128 threads / 4 warps
// (wm x wn = 2x2, warp tile 32x32). 3xTF32 split (hihi + hilo + lohi).

// ---- B-side conversion + store (per-thread row staging) ----------------
__device__ __forceinline__ void sts_b_convert(uint4* Bsm, const float4* braw,
                                              int r, int qp) {
    int xr = (r & 3) ^ ((r >> 2) & 3);
#pragma unroll
    for (int oo = 0; oo < 2; oo++) {
        float f[8];
        f[0] = braw[oo*2].x;   f[1] = braw[oo*2].y;
        f[2] = braw[oo*2].z;   f[3] = braw[oo*2].w;
        f[4] = braw[oo*2+1].x; f[5] = braw[oo*2+1].y;
        f[6] = braw[oo*2+1].z; f[7] = braw[oo*2+1].w;
        uint32_t hi[8], lo[8];
#pragma unroll
        for (int p = 0; p < 8; p++) {
            hi[p] = f2tf32(f[p]);
            lo[p] = f2tf32(f[p] - __uint_as_float(hi[p]));
        }
        int q = qp * 2 + oo;
        int sbase = q * 256 + r * 4;
#pragma unroll
        for (int t2 = 0; t2 < 4; t2++) {
            uint4 ch;
            ch.x = hi[t2]; ch.y = hi[t2 + 4];
            ch.z = lo[t2]; ch.w = lo[t2 + 4];
            Bsm[sbase + (t2 ^ xr)] = ch;
        }
    }
}

// ---- MMA on one staged ktile -------------------------------------------
__device__ __forceinline__ void mma_ktile(const uint4* As, const uint4* Bsm,
                                          float4 c[2][4], int wm, int wn,
                                          int lane, int g, int tg) {
#pragma unroll
    for (int q = 0; q < 4; q++) {
        uint4 ah[2], al[2], bq[4];
#pragma unroll
        for (int mi = 0; mi < 2; mi++) {
            int s = wm * 2 + mi;
            ah[mi] = As[((q * 4 + s) * 2 + 0) * 32 + lane];
            al[mi] = As[((q * 4 + s) * 2 + 1) * 32 + lane];
        }
#pragma unroll
        for (int ni = 0; ni < 4; ni++) {
            int rr = wn * 32 + ni * 8 + g;
            int sw = tg ^ (rr & 3) ^ ((rr >> 2) & 3);
            bq[ni] = Bsm[q * 256 + rr * 4 + sw];
        }
#pragma unroll
        for (int mi = 0; mi < 2; mi++)
#pragma unroll
            for (int ni = 0; ni < 4; ni++) {
                mma_tf32(c[mi][ni], ah[mi], bq[ni].x, bq[ni].y);
                mma_tf32(c[mi][ni], ah[mi], bq[ni].z, bq[ni].w);
                mma_tf32(c[mi][ni], al[mi], bq[ni].x, bq[ni].y);
            }
    }
}

// GEMM1: x[t,j,ch] = mask * (cnn[lookup[order[j],t]] @ fc_w^T + fc_b)[ch]
__global__ void __launch_bounds__(128) k_gemm1(
    const float* __restrict__ cnn, const float* __restrict__ fcb,
    const int* __restrict__ lookup, float* __restrict__ xout) {
    __shared__ uint4 As[1024];
    __shared__ uint4 Bsm[1024];
    __shared__ int   simg[64];

    int j   = blockIdx.z;
    int t0  = blockIdx.y * 64;
    int m0  = blockIdx.x * 64;
    int tid = threadIdx.x;
    int len = g_lens[j];

    if (t0 >= len) {
        for (int i = tid; i < 1024; i += 128) {
            int r  = i >> 4;
            int cc = (i & 15) * 4;
            int t  = t0 + r;
            *(float4*)&xout[((size_t)t * BB + j) * DD + m0 + cc] =
                make_float4(0.f, 0.f, 0.f, 0.f);
        }
        return;
    }
    if (tid < 64) simg[tid] = lookup[g_order[j] * TT + t0 + tid];
    __syncthreads();

    int lane = tid & 31;
    int w    = tid >> 5;
    int wm   = w >> 1, wn = w & 1;
    int g    = lane >> 2, tg = lane & 3;
    int r    = tid >> 1, qp = tid & 1;
    size_t brow = (size_t)simg[r] * FEAT;

    float4 c[2][4];
#pragma unroll
    for (int mi = 0; mi < 2; mi++)
#pragma unroll
        for (int ni = 0; ni < 4; ni++) c[mi][ni] = make_float4(0.f,0.f,0.f,0.f);

    uint4  areg[8];
    float4 braw[4];
    // prologue: tile 0
    {
        const uint4* at = g_wfc + ((size_t)blockIdx.x * 64 + 0) * 1024;
#pragma unroll
        for (int u = 0; u < 8; u++) areg[u] = at[tid + 128 * u];
        int kb = qp * 16;
#pragma unroll
        for (int u = 0; u < 4; u++)
            braw[u] = *(const float4*)&cnn[brow + kb + u * 4];
    }

    for (int kt = 0; kt < 64; kt++) {
        __syncthreads();
#pragma unroll
        for (int u = 0; u < 8; u++) As[tid + 128 * u] = areg[u];
        sts_b_convert(Bsm, braw, r, qp);
        __syncthreads();
        if (kt + 1 < 64) {
            const uint4* at = g_wfc + ((size_t)blockIdx.x * 64 + kt + 1) * 1024;
#pragma unroll
            for (int u = 0; u < 8; u++) areg[u] = at[tid + 128 * u];
            int kb = (kt + 1) * 32 + qp * 16;
#pragma unroll
            for (int u = 0; u < 4; u++)
                braw[u] = *(const float4*)&cnn[brow + kb + u * 4];
        }
        mma_ktile(As, Bsm, c, wm, wn, lane, g, tg);
    }

    // epilogue: D[m=ch][n=t]; c0=D[g][2tg], c1=D[g][2tg+1], c2=D[g+8][2tg], c3=D[g+8][2tg+1]
#pragma unroll
    for (int mi = 0; mi < 2; mi++) {
        int ch  = m0 + wm * 32 + mi * 16 + g;
        float b0 = fcb[ch], b8 = fcb[ch + 8];
#pragma unroll
        for (int ni = 0; ni < 4; ni++) {
            int tA = t0 + wn * 32 + ni * 8 + 2 * tg;
            bool v0 = (tA < len), v1 = (tA + 1 < len);
            size_t r0o = ((size_t)tA * BB + j) * DD;
            size_t r1o = ((size_t)(tA + 1) * BB + j) * DD;
            xout[r0o + ch]     = v0 ? c[mi][ni].x + b0 : 0.f;
            xout[r1o + ch]     = v1 ? c[mi][ni].y + b0 : 0.f;
            xout[r0o + ch + 8] = v0 ? c[mi][ni].z + b8 : 0.f;
            xout[r1o + ch + 8] = v1 ? c[mi][ni].w + b8 : 0.f;
        }
    }
}

// GEMM2: G[dir][j,t,ch] = x[t,j,:] @ w_ih[dir]^T  (ch in 0..2047)
__global__ void __launch_bounds__(128) k_gemm2(const float* __restrict__ x) {
    __shared__ uint4 As[1024];
    __shared__ uint4 Bsm[1024];

    int dir = blockIdx.z;
    int j   = blockIdx.y >> 3;
    int t0  = (blockIdx.y & 7) * 64;
    int m0  = blockIdx.x * 64;
    int tid = threadIdx.x;
    int len = g_lens[j];
    if (t0 >= len) return;

    int lane = tid & 31;
    int w    = tid >> 5;
    int wm   = w >> 1, wn = w & 1;
    int g    = lane >> 2, tg = lane & 3;
    int r    = tid >> 1, qp = tid & 1;
    size_t brow = ((size_t)(t0 + r) * BB + j) * DD;

    float4 c[2][4];
#pragma unroll
    for (int mi = 0; mi < 2; mi++)
#pragma unroll
        for (int ni = 0; ni < 4; ni++) c[mi][ni] = make_float4(0.f,0.f,0.f,0.f);

    const uint4* wbase = g_wih[dir];
    uint4  areg[8];
    float4 braw[4];
    {
        const uint4* at = wbase + ((size_t)blockIdx.x * 16 + 0) * 1024;
#pragma unroll
        for (int u = 0; u < 8; u++) areg[u] = at[tid + 128 * u];
        int kb = qp * 16;
#pragma unroll
        for (int u = 0; u < 4; u++)
            braw[u] = *(const float4*)&x[brow + kb + u * 4];
    }

    for (int kt = 0; kt < 16; kt++) {
        __syncthreads();
#pragma unroll
        for (int u = 0; u < 8; u++) As[tid + 128 * u] = areg[u];
        sts_b_convert(Bsm, braw, r, qp);
        __syncthreads();
        if (kt + 1 < 16) {
            const uint4* at = wbase + ((size_t)blockIdx.x * 16 + kt + 1) * 1024;
#pragma unroll
            for (int u = 0; u < 8; u++) areg[u] = at[tid + 128 * u];
            int kb = (kt + 1) * 32 + qp * 16;
#pragma unroll
            for (int u = 0; u < 4; u++)
                braw[u] = *(const float4*)&x[brow + kb + u * 4];
        }
        mma_ktile(As, Bsm, c, wm, wn, lane, g, tg);
    }

    float* Gd = g_G + (size_t)dir * GSZ;
#pragma unroll
    for (int mi = 0; mi < 2; mi++) {
        int ch = m0 + wm * 32 + mi * 16 + g;
#pragma unroll
        for (int ni = 0; ni < 4; ni++) {
            int tA = t0 + wn * 32 + ni * 8 + 2 * tg;
            size_t r0o = ((size_t)j * TT + tA) * G4H;
            size_t r1o = ((size_t)j * TT + tA + 1) * G4H;
            Gd[r0o + ch]     = c[mi][ni].x;
            Gd[r1o + ch]     = c[mi][ni].y;
            Gd[r0o + ch + 8] = c[mi][ni].z;
            Gd[r1o + ch + 8] = c[mi][ni].w;
        }
    }
}

// ---------------- persistent scan kernel --------------------------------
__device__ __forceinline__ void grid_sync_step(int step) {
    __syncthreads();
    if (threadIdx.x == 0) {
        __threadfence();
        atomicAdd(&g_bar, 1u);
        unsigned target = (unsigned)(NCTA_SCAN * (step + 1));
        while (*(volatile unsigned*)&g_bar < target) { __nanosleep(32); }
    }
    __syncthreads();
}

__global__ void __launch_bounds__(256, 1) k_scan(
    const float* __restrict__ c0,
    const float* __restrict__ whhf, const float* __restrict__ whhb,
    const float* __restrict__ bihf, const float* __restrict__ bhhf,
    const float* __restrict__ bihb, const float* __restrict__ bhhb,
    float* __restrict__ out) {
    extern __shared__ float sm[];
    float* w_s = sm;            // [4 gates][8 hc][512 k] = 16384 floats
    float* h_s = sm + 16384;    // [32 b][516 padded]

    int bid   = blockIdx.x;
    int dir   = bid >> 6;
    int ctad  = bid & 63;
    int hcb   = ctad * 8;
    int tid   = threadIdx.x;
    int wp    = tid >> 5;
    int lane  = tid & 31;
    int hc    = hcb + wp;
    int b     = lane;

    const float* whh = dir ? whhb : whhf;
    for (int i = tid; i < 4096; i += 256) {
        int gg  = i >> 10;
        int rem = i & 1023;
        int hcl = rem >> 7;
        int k   = (rem & 127) * 4;
        int gc  = gg * HH + hcb + hcl;
        *(float4*)&w_s[(gg * 8 + hcl) * 512 + k] =
            *(const float4*)&whh[(size_t)gc * HH + k];
    }

    int   len = g_lens[b];
    float bias0, bias1, bias2, bias3;
    {
        const float* bih = dir ? bihb : bihf;
        const float* bhh = dir ? bhhb : bhhf;
        bias0 = bih[0 * HH + hc] + bhh[0 * HH + hc];
        bias1 = bih[1 * HH + hc] + bhh[1 * HH + hc];
        bias2 = bih[2 * HH + hc] + bhh[2 * HH + hc];
        bias3 = bih[3 * HH + hc] + bhh[3 * HH + hc];
    }
    float creg = c0[dir * 16384 + b * HH + hc];
    float hreg = g_hbuf[(dir * 2 + 0) * 16384 + b * HH + hc];
    const float* Gd = g_G + (size_t)dir * GSZ;

    const ulonglong2* W0 = (const ulonglong2*)&w_s[(0 * 8 + wp) * 512];
    const ulonglong2* W1 = (const ulonglong2*)&w_s[(1 * 8 + wp) * 512];
    const ulonglong2* W2 = (const ulonglong2*)&w_s[(2 * 8 + wp) * 512];
    const ulonglong2* W3 = (const ulonglong2*)&w_s[(3 * 8 + wp) * 512];
    const ulonglong2* hv2 = (const ulonglong2*)&h_s[b * 516];

    for (int s = 0; s < TT; s++) {
        int p = s & 1;
        const float* hin = &g_hbuf[(dir * 2 + p) * 16384];
        for (int i = tid; i < 4096; i += 256) {
            float4 v = __ldcg((const float4*)&hin[i * 4]);
            int bb = i >> 7;
            int kk = (i & 127) * 4;
            *(float4*)&h_s[bb * 516 + kk] = v;
        }
        __syncthreads();

        bool  active = (s < len);
        int   tt     = dir ? (len - 1 - s) : s;
        float gp0 = 0.f, gp1 = 0.f, gp2 = 0.f, gp3 = 0.f;
        if (active) {
            size_t base = ((size_t)b * TT + tt) * G4H + hc;
            gp0 = Gd[base + 0 * HH];
            gp1 = Gd[base + 1 * HH];
            gp2 = Gd[base + 2 * HH];
            gp3 = Gd[base + 3 * HH];
        }

        unsigned long long s00 = 0, s01 = 0, s10 = 0, s11 = 0;
        unsigned long long s20 = 0, s21 = 0, s30 = 0, s31 = 0;
#pragma unroll 4
        for (int k4 = 0; k4 < 128; k4++) {
            ulonglong2 h2 = hv2[k4];
            ulonglong2 v0 = W0[k4]; FMA2(s00, h2.x, v0.x); FMA2(s01, h2.y, v0.y);
            ulonglong2 v1 = W1[k4]; FMA2(s10, h2.x, v1.x); FMA2(s11, h2.y, v1.y);
            ulonglong2 v2 = W2[k4]; FMA2(s20, h2.x, v2.x); FMA2(s21, h2.y, v2.y);
            ulonglong2 v3 = W3[k4]; FMA2(s30, h2.x, v3.x); FMA2(s31, h2.y, v3.y);
        }
        float gi = sum2(s00) + sum2(s01) + gp0 + bias0;
        float gf = sum2(s10) + sum2(s11) + gp1 + bias1;
        float gg = sum2(s20) + sum2(s21) + gp2 + bias2;
        float go = sum2(s30) + sum2(s31) + gp3 + bias3;
        float i_ = 1.f / (1.f + __expf(-gi));
        float f_ = 1.f / (1.f + __expf(-gf));
        float g_ = tanhf(gg);
        float o_ = 1.f / (1.f + __expf(-go));
        float cn = f_ * creg + i_ * g_;
        float hn = o_ * tanhf(cn);

        if (dir == 0) {
            out[OUT_OFF + ((size_t)s * BB + b) * 1024 + hc] = active ? hn : 0.f;
        } else {
            int tw = active ? (len - 1 - s) : s;
            out[OUT_OFF + ((size_t)tw * BB + b) * 1024 + 512 + hc] = active ? hn : 0.f;
        }
        if (active) { creg = cn; hreg = hn; }

        g_hbuf[(dir * 2 + (1 - p)) * 16384 + b * HH + hc] = hreg;
        grid_sync_step(s);
    }
    out[HN_OFF + dir * 16384 + b * HH + hc] = hreg;
    out[CN_OFF + dir * 16384 + b * HH + hc] = creg;
}

// ---------------- launcher ----------------------------------------------
extern "C" void kernel_launch(void* const* d_in, const int* in_sizes, int n_in,
                              void* d_out, int out_size) {
    const float* cnn  = (const float*)d_in[0];
    const float* fcw  = (const float*)d_in[1];
    const float* fcb  = (const float*)d_in[2];
    const float* h0   = (const float*)d_in[3];
    const float* c0   = (const float*)d_in[4];
    const float* wihf = (const float*)d_in[5];
    const float* whhf = (const float*)d_in[6];
    const float* bihf = (const float*)d_in[7];
    const float* bhhf = (const float*)d_in[8];
    const float* wihb = (const float*)d_in[9];
    const float* whhb = (const float*)d_in[10];
    const float* bihb = (const float*)d_in[11];
    const float* bhhb = (const float*)d_in[12];
    const int* seq_lens = (const int*)d_in[13];
    const int* lookup   = (const int*)d_in[14];
    float* out = (float*)d_out;

    cudaFuncSetAttribute(k_scan, cudaFuncAttributeMaxDynamicSharedMemorySize,
                         SCAN_SMEM);

    k_reset<<<1, 256>>>(seq_lens, h0, out);
    k_prep<<<dim3(2048, 3), 256>>>(fcw, wihf, wihb);
    k_gemm1<<<dim3(8, 8, 32), 128>>>(cnn, fcb, lookup, out + X_OFF);
    k_gemm2<<<dim3(32, 256, 2), 128>>>(out + X_OFF);
    k_scan<<<NCTA_SCAN, 256, SCAN_SMEM>>>(c0, whhf, whhb, bihf, bhhf, bihb,
                                          bhhb, out);
}